// round 14
// baseline (speedup 1.0000x reference)
#include <cuda_runtime.h>
#include <cuda_bf16.h>
#include <cstdint>

#define GN 50000
#define GE 1600000
#define FULLMASK 0xFFFFFFFFu

typedef unsigned long long u64;

// ---------------- f32x2 packed-FMA helpers ----------------
__device__ __forceinline__ u64 pack2(float lo, float hi) {
    u64 r; asm("mov.b64 %0, {%1, %2};" : "=l"(r) : "f"(lo), "f"(hi)); return r;
}
__device__ __forceinline__ u64 fma2(u64 a, u64 b, u64 c) {
    u64 r; asm("fma.rn.f32x2 %0, %1, %2, %3;" : "=l"(r) : "l"(a), "l"(b), "l"(c)); return r;
}
__device__ __forceinline__ float2 unpack2(u64 v) {
    float2 f; asm("mov.b64 {%0, %1}, %2;" : "=f"(f.x), "=f"(f.y) : "l"(v)); return f;
}

// ---------------- mma.sync + ldmatrix helpers (baseline PTX) ----------
__device__ __forceinline__ void mma_bf16(float* c, const uint32_t* a, const uint32_t* b) {
    asm volatile(
        "mma.sync.aligned.m16n8k16.row.col.f32.bf16.bf16.f32 "
        "{%0,%1,%2,%3}, {%4,%5,%6,%7}, {%8,%9}, {%0,%1,%2,%3};\n"
        : "+f"(c[0]), "+f"(c[1]), "+f"(c[2]), "+f"(c[3])
        : "r"(a[0]), "r"(a[1]), "r"(a[2]), "r"(a[3]), "r"(b[0]), "r"(b[1]));
}
__device__ __forceinline__ void ldsm_x4(uint32_t* r, uint32_t addr) {
    asm volatile("ldmatrix.sync.aligned.m8n8.x4.shared.b16 {%0,%1,%2,%3}, [%4];"
                 : "=r"(r[0]), "=r"(r[1]), "=r"(r[2]), "=r"(r[3]) : "r"(addr));
}
__device__ __forceinline__ uint32_t smem_u32(const void* p) {
    uint32_t a;
    asm("{ .reg .u64 t; cvta.to.shared.u64 t, %1; cvt.u32.u64 %0, t; }" : "=r"(a) : "l"(p));
    return a;
}
__device__ __forceinline__ uint32_t bfpack(__nv_bfloat16 a, __nv_bfloat16 b) {
    __nv_bfloat162 p(a, b);
    return *(uint32_t*)&p;
}

// ---------------- scratch ----------------
__device__ float g_f128[GN * 128];
__device__ float g_xA[GN * 128];
__device__ float g_tr[GN * 128];
__device__ float g_h[GN * 64];
__device__ float g_mh[GN * 128];
__device__ float g_xB[GN * 128];
__device__ float g_ob[GN * 128];
__device__ int   g_cnt[GN];
__device__ int   g_rowptr[GN + 1];
__device__ int   g_cursor[GN];
__device__ int   g_col[GE];
__device__ float g_invdeg[GN];

// ---------------- CSR build ----------------
__global__ void count_kernel(const int* __restrict__ dst, int e) {
    int i = blockIdx.x * blockDim.x + threadIdx.x;
    if (i < e) atomicAdd(&g_cnt[dst[i]], 1);
}

__global__ void scan_kernel(int n) {
    __shared__ int wsum[32];
    __shared__ int carry_s;
    int tid = threadIdx.x, lane = tid & 31, wid = tid >> 5;
    if (tid == 0) carry_s = 0;
    __syncthreads();
    for (int base = 0; base < n; base += 1024) {
        int i = base + tid;
        int v = (i < n) ? g_cnt[i] : 0;
        int x = v;
        #pragma unroll
        for (int o = 1; o < 32; o <<= 1) {
            int t = __shfl_up_sync(FULLMASK, x, o);
            if (lane >= o) x += t;
        }
        if (lane == 31) wsum[wid] = x;
        __syncthreads();
        if (wid == 0) {
            int y = wsum[lane];
            #pragma unroll
            for (int o = 1; o < 32; o <<= 1) {
                int t = __shfl_up_sync(FULLMASK, y, o);
                if (lane >= o) y += t;
            }
            wsum[lane] = y;
        }
        __syncthreads();
        int incl = x + (wid > 0 ? wsum[wid - 1] : 0);
        int total = wsum[31];
        int carry = carry_s;
        if (i < n) {
            int rp = carry + incl - v;
            g_rowptr[i] = rp;
            g_cursor[i] = rp;
            int d = v > 1 ? v : 1;
            g_invdeg[i] = 1.0f / (float)d;
        }
        __syncthreads();
        if (tid == 0) carry_s = carry + total;
        __syncthreads();
    }
    if (threadIdx.x == 0) g_rowptr[n] = carry_s;
}

__global__ void scatter_kernel(const int* __restrict__ src, const int* __restrict__ dst, int e) {
    int i = blockIdx.x * blockDim.x + threadIdx.x;
    if (i < e) {
        int p = atomicAdd(&g_cursor[dst[i]], 1);
        g_col[p] = src[i];
    }
}

// ---------------- small front features ----------------
__global__ void front_small_kernel(const float* __restrict__ num, const float* __restrict__ cat,
                                   const float* __restrict__ Wn, const float* __restrict__ bn,
                                   const float* __restrict__ Wc, const float* __restrict__ bc, int n) {
    int i = blockIdx.x * blockDim.x + threadIdx.x;
    if (i >= n) return;
    float nv0 = num[i * 4 + 0], nv1 = num[i * 4 + 1], nv2 = num[i * 4 + 2], nv3 = num[i * 4 + 3];
    float cv0 = cat[i * 3 + 0], cv1 = cat[i * 3 + 1], cv2 = cat[i * 3 + 2];
    float* f = g_f128 + (size_t)i * 128;
    for (int o = 0; o < 42; o++) {
        float s = bn[o];
        s = fmaf(nv0, Wn[o], s);
        s = fmaf(nv1, Wn[42 + o], s);
        s = fmaf(nv2, Wn[84 + o], s);
        s = fmaf(nv3, Wn[126 + o], s);
        f[32 + o] = s > 0.f ? s : 0.01f * s;
        float s2 = bc[o];
        s2 = fmaf(cv0, Wc[o], s2);
        s2 = fmaf(cv1, Wc[42 + o], s2);
        s2 = fmaf(cv2, Wc[84 + o], s2);
        f[74 + o] = s2 > 0.f ? s2 : 0.01f * s2;
    }
    #pragma unroll
    for (int o = 116; o < 128; o++) f[o] = 0.f;
}

// ---------------- FFMA2 GEMM (des 768->32) ----------------
template<int CPL, int ACT>
__global__ void __launch_bounds__(256, 2) gemm_kernel(
    const float* __restrict__ A, int lda, int nrows,
    const float* __restrict__ W0, int rows0, int cols0,
    const float* __restrict__ W1, int rows1, int cols1, int colcat,
    const float* __restrict__ bias,
    float* __restrict__ out, int ldo,
    int K, int C)
{
    extern __shared__ char smem[];
    u64* Wp = (u64*)smem;
    float* Bs = (float*)(Wp + (K / 2) * C);
    int tid = threadIdx.x;
    int npairs = (K / 2) * C;
    for (int idx = tid; idx < npairs; idx += 256) {
        int kp = idx / C, c = idx - kp * C;
        float v0, v1;
        int k0 = 2 * kp, k1 = 2 * kp + 1;
        if (colcat) {
            v0 = (c < cols0) ? W0[k0 * cols0 + c] : W1[k0 * cols1 + (c - cols0)];
            v1 = (c < cols0) ? W0[k1 * cols0 + c] : W1[k1 * cols1 + (c - cols0)];
        } else {
            v0 = (k0 < rows0) ? W0[k0 * cols0 + c]
               : (k0 < rows0 + rows1) ? W1[(k0 - rows0) * cols1 + c] : 0.f;
            v1 = (k1 < rows0) ? W0[k1 * cols0 + c]
               : (k1 < rows0 + rows1) ? W1[(k1 - rows0) * cols1 + c] : 0.f;
        }
        Wp[idx] = pack2(v0, v1);
    }
    for (int c = tid; c < C; c += 256) Bs[c] = bias ? bias[c] : 0.f;
    __syncthreads();

    const int warp = tid >> 5, lane = tid & 31;
    const int c0 = lane * CPL;
    const int KQ = K / 4;

    for (int tile = blockIdx.x * 64; tile < nrows; tile += gridDim.x * 64) {
        const int rowbase = tile + warp * 8;
        const float* Ap[8];
        #pragma unroll
        for (int r = 0; r < 8; r++) {
            int rr = rowbase + r;
            if (rr >= nrows) rr = nrows - 1;
            Ap[r] = A + (size_t)rr * lda;
        }
        u64 acc[8];
        #pragma unroll
        for (int r = 0; r < 8; r++) acc[r] = 0ull;

        #pragma unroll 2
        for (int t = 0; t < KQ; t++) {
            u64 wA = Wp[(2 * t) * C + c0];
            u64 wB = Wp[(2 * t + 1) * C + c0];
            #pragma unroll
            for (int r = 0; r < 8; r++) {
                ulonglong2 av = *(const ulonglong2*)(Ap[r] + 4 * t);
                acc[r] = fma2(av.x, wA, acc[r]);
                acc[r] = fma2(av.y, wB, acc[r]);
            }
        }

        float bb = Bs[c0];
        #pragma unroll
        for (int r = 0; r < 8; r++) {
            int rr = rowbase + r;
            if (rr < nrows) {
                float2 v = unpack2(acc[r]);
                float o = v.x + v.y + bb;
                if (ACT == 1) o = o > 0.f ? o : 0.01f * o;
                else if (ACT == 2) o = o > 0.f ? o : 0.f;
                out[(size_t)rr * ldo + c0] = o;
            }
        }
    }
}

// ---------------- mma.sync tensor GEMM v3: double-buffered A ----------------
// Split-bf16: D = Ahi*Bhi + Ahi*Blo + Alo*Bhi. 512 thr, ldmatrix, split columns.
// A double buffered: prefetch next tile's A to regs during compute, store after epilogue.
#define RSTRIDE 272
#define AB_SZ    34816              // one A half (hi or lo) = 128*272
#define ABUF_SZ  69632              // hi+lo per buffer
#define MMA_BHI  139264             // after 2 A buffers
#define MMA_BLO  174080
#define MMA_BIAS 208896
#define MMA_TOT  209408

template<int ACT>
__global__ void __launch_bounds__(512, 1) mma_gemm_kernel(
    const float* __restrict__ A, int lda, int nrows,
    const float* __restrict__ W0, int rows0, int cols0,
    const float* __restrict__ W1, int cols1, int colcat,
    const float* __restrict__ bias,
    float* __restrict__ out, int ldo)
{
    extern __shared__ char smem[];
    const uint32_t sbase = smem_u32(smem);
    const int tid = threadIdx.x;
    const int wid = tid >> 5, lane = tid & 31;
    const int g = lane >> 2, t = lane & 3;
    const int rowblk = (wid >> 1) * 16;
    const int colblk = (wid & 1) * 64;

    // within-buffer ldmatrix offsets
    const uint32_t a_thr = (uint32_t)((rowblk + (lane & 15)) * RSTRIDE + ((lane >> 4) * 8) * 2);
    const uint32_t b_thr = (uint32_t)((lane < 16 ? MMA_BHI : MMA_BLO)
                                      + (lane & 7) * RSTRIDE + (((lane >> 3) & 1) * 8) * 2);

    float* Bsf = (float*)(smem + MMA_BIAS);
    for (int c = tid; c < 128; c += 512) Bsf[c] = bias ? bias[c] : 0.f;

    // stage weights once per CTA
    for (int idx = tid; idx < 128 * 128; idx += 512) {
        int k = idx >> 7, n = idx & 127;
        float v;
        if (colcat) v = (n < cols0) ? W0[k * cols0 + n] : W1[k * cols1 + (n - cols0)];
        else        v = (k < rows0) ? W0[k * 128 + n]
                      : (W1 ? W1[(k - rows0) * 128 + n] : 0.f);
        __nv_bfloat16 hi = __float2bfloat16(v);
        __nv_bfloat16 lo = __float2bfloat16(v - __bfloat162float(hi));
        int off = n * RSTRIDE + k * 2;
        *(__nv_bfloat16*)(smem + MMA_BHI + off) = hi;
        *(__nv_bfloat16*)(smem + MMA_BLO + off) = lo;
    }

    const int stride = gridDim.x * 128;
    int tile = blockIdx.x * 128;
    int p = 0;

    // prologue: stage first tile into buffer 0
    if (tile < nrows) {
        #pragma unroll
        for (int i = 0; i < 8; i++) {
            int idx = tid + i * 512;
            int r = idx >> 5, k4 = (idx & 31) * 4;
            int rr = tile + r; if (rr >= nrows) rr = nrows - 1;
            float4 v = *(const float4*)(A + (size_t)rr * lda + k4);
            __nv_bfloat16 h0 = __float2bfloat16(v.x), h1 = __float2bfloat16(v.y);
            __nv_bfloat16 h2 = __float2bfloat16(v.z), h3 = __float2bfloat16(v.w);
            __nv_bfloat16 l0 = __float2bfloat16(v.x - __bfloat162float(h0));
            __nv_bfloat16 l1 = __float2bfloat16(v.y - __bfloat162float(h1));
            __nv_bfloat16 l2 = __float2bfloat16(v.z - __bfloat162float(h2));
            __nv_bfloat16 l3 = __float2bfloat16(v.w - __bfloat162float(h3));
            int off = r * RSTRIDE + k4 * 2;
            *(uint2*)(smem + off) = make_uint2(bfpack(h0, h1), bfpack(h2, h3));
            *(uint2*)(smem + AB_SZ + off) = make_uint2(bfpack(l0, l1), bfpack(l2, l3));
        }
    }
    __syncthreads();

    for (; tile < nrows; tile += stride) {
        int next = tile + stride;
        bool pre = next < nrows;
        float4 v[8];
        if (pre) {
            #pragma unroll
            for (int i = 0; i < 8; i++) {
                int idx = tid + i * 512;
                int r = idx >> 5, k4 = (idx & 31) * 4;
                int rr = next + r; if (rr >= nrows) rr = nrows - 1;
                v[i] = *(const float4*)(A + (size_t)rr * lda + k4);
            }
        }

        float acc[8][4];
        #pragma unroll
        for (int nt = 0; nt < 8; nt++)
            #pragma unroll
            for (int j = 0; j < 4; j++) acc[nt][j] = 0.f;

        const uint32_t abase = sbase + (uint32_t)(p * ABUF_SZ);
        #pragma unroll
        for (int ks = 0; ks < 8; ks++) {
            uint32_t koff = (uint32_t)(32 * ks);
            uint32_t ah[4], al[4];
            ldsm_x4(ah, abase + a_thr + koff);
            ldsm_x4(al, abase + AB_SZ + a_thr + koff);
            #pragma unroll
            for (int nt = 0; nt < 8; nt++) {
                uint32_t bf[4];
                ldsm_x4(bf, sbase + b_thr + (uint32_t)((colblk + nt * 8) * RSTRIDE) + koff);
                mma_bf16(acc[nt], ah, bf);
                mma_bf16(acc[nt], ah, bf + 2);
                mma_bf16(acc[nt], al, bf);
            }
        }

        // epilogue
        int r0 = tile + rowblk + g;
        int r1 = r0 + 8;
        #pragma unroll
        for (int nt = 0; nt < 8; nt++) {
            int cc = colblk + nt * 8 + t * 2;
            float o0 = acc[nt][0] + Bsf[cc], o1 = acc[nt][1] + Bsf[cc + 1];
            float o2 = acc[nt][2] + Bsf[cc], o3 = acc[nt][3] + Bsf[cc + 1];
            if (ACT == 1) {
                o0 = o0 > 0.f ? o0 : 0.01f * o0; o1 = o1 > 0.f ? o1 : 0.01f * o1;
                o2 = o2 > 0.f ? o2 : 0.01f * o2; o3 = o3 > 0.f ? o3 : 0.01f * o3;
            } else if (ACT == 2) {
                o0 = o0 > 0.f ? o0 : 0.f; o1 = o1 > 0.f ? o1 : 0.f;
                o2 = o2 > 0.f ? o2 : 0.f; o3 = o3 > 0.f ? o3 : 0.f;
            }
            if (r0 < nrows) *(float2*)(out + (size_t)r0 * ldo + cc) = make_float2(o0, o1);
            if (r1 < nrows) *(float2*)(out + (size_t)r1 * ldo + cc) = make_float2(o2, o3);
        }

        if (pre) {
            int pb = (p ^ 1) * ABUF_SZ;
            #pragma unroll
            for (int i = 0; i < 8; i++) {
                int idx = tid + i * 512;
                int r = idx >> 5, k4 = (idx & 31) * 4;
                __nv_bfloat16 h0 = __float2bfloat16(v[i].x), h1 = __float2bfloat16(v[i].y);
                __nv_bfloat16 h2 = __float2bfloat16(v[i].z), h3 = __float2bfloat16(v[i].w);
                __nv_bfloat16 l0 = __float2bfloat16(v[i].x - __bfloat162float(h0));
                __nv_bfloat16 l1 = __float2bfloat16(v[i].y - __bfloat162float(h1));
                __nv_bfloat16 l2 = __float2bfloat16(v[i].z - __bfloat162float(h2));
                __nv_bfloat16 l3 = __float2bfloat16(v[i].w - __bfloat162float(h3));
                int off = pb + r * RSTRIDE + k4 * 2;
                *(uint2*)(smem + off) = make_uint2(bfpack(h0, h1), bfpack(h2, h3));
                *(uint2*)(smem + AB_SZ + off) = make_uint2(bfpack(l0, l1), bfpack(l2, l3));
            }
        }
        __syncthreads();
        p ^= 1;
    }
}

// ---------------- aggregation (warp per node, 4-edge unroll) ----------------
__global__ void agg_a_kernel(const float* __restrict__ tr, const float* __restrict__ bl,
                             float* __restrict__ h, int n) {
    int w = (blockIdx.x * blockDim.x + threadIdx.x) >> 5;
    if (w >= n) return;
    int lane = threadIdx.x & 31;
    int c = lane * 2;
    int e = g_rowptr[w], end = g_rowptr[w + 1];
    float s0 = 0.f, s1 = 0.f;
    for (; e + 4 <= end; e += 4) {
        int j0 = g_col[e], j1 = g_col[e + 1], j2 = g_col[e + 2], j3 = g_col[e + 3];
        float2 v0 = *(const float2*)&tr[(size_t)j0 * 128 + c];
        float2 v1 = *(const float2*)&tr[(size_t)j1 * 128 + c];
        float2 v2 = *(const float2*)&tr[(size_t)j2 * 128 + c];
        float2 v3 = *(const float2*)&tr[(size_t)j3 * 128 + c];
        s0 += (v0.x + v1.x) + (v2.x + v3.x);
        s1 += (v0.y + v1.y) + (v2.y + v3.y);
    }
    for (; e < end; e++) {
        int j = g_col[e];
        float2 v = *(const float2*)&tr[(size_t)j * 128 + c];
        s0 += v.x; s1 += v.y;
    }
    float id = g_invdeg[w];
    float2 r = *(const float2*)&tr[(size_t)w * 128 + 64 + c];
    float o0 = fmaf(s0, id, bl[c] + r.x);
    float o1 = fmaf(s1, id, bl[c + 1] + r.y);
    o0 = o0 > 0.f ? o0 : 0.f;
    o1 = o1 > 0.f ? o1 : 0.f;
    *(float2*)&h[(size_t)w * 64 + c] = make_float2(o0, o1);
}

__global__ void agg_b_kernel(const float* __restrict__ h, float* __restrict__ mh, int n) {
    int w = (blockIdx.x * blockDim.x + threadIdx.x) >> 5;
    if (w >= n) return;
    int lane = threadIdx.x & 31;
    int c = lane * 2;
    int e = g_rowptr[w], end = g_rowptr[w + 1];
    float s0 = 0.f, s1 = 0.f;
    for (; e + 4 <= end; e += 4) {
        int j0 = g_col[e], j1 = g_col[e + 1], j2 = g_col[e + 2], j3 = g_col[e + 3];
        float2 v0 = *(const float2*)&h[(size_t)j0 * 64 + c];
        float2 v1 = *(const float2*)&h[(size_t)j1 * 64 + c];
        float2 v2 = *(const float2*)&h[(size_t)j2 * 64 + c];
        float2 v3 = *(const float2*)&h[(size_t)j3 * 64 + c];
        s0 += (v0.x + v1.x) + (v2.x + v3.x);
        s1 += (v0.y + v1.y) + (v2.y + v3.y);
    }
    for (; e < end; e++) {
        int j = g_col[e];
        float2 v = *(const float2*)&h[(size_t)j * 64 + c];
        s0 += v.x; s1 += v.y;
    }
    float id = g_invdeg[w];
    float2 hv = *(const float2*)&h[(size_t)w * 64 + c];
    *(float2*)&mh[(size_t)w * 128 + c] = make_float2(s0 * id, s1 * id);
    *(float2*)&mh[(size_t)w * 128 + 64 + c] = hv;
}

// ---------------- final 128->2 projection ----------------
__global__ void out_kernel(const float* __restrict__ ob, const float* __restrict__ W,
                           const float* __restrict__ b, float* __restrict__ out, int n) {
    int w = (blockIdx.x * blockDim.x + threadIdx.x) >> 5;
    if (w >= n) return;
    int lane = threadIdx.x & 31;
    const float* row = ob + (size_t)w * 128;
    float a0 = row[lane];
    float a1 = row[lane + 32];
    float a2 = row[lane + 64];
    float a3 = row[lane + 96];
    float p0 = a0 * W[lane * 2 + 0] + a1 * W[(lane + 32) * 2 + 0]
             + a2 * W[(lane + 64) * 2 + 0] + a3 * W[(lane + 96) * 2 + 0];
    float p1 = a0 * W[lane * 2 + 1] + a1 * W[(lane + 32) * 2 + 1]
             + a2 * W[(lane + 64) * 2 + 1] + a3 * W[(lane + 96) * 2 + 1];
    #pragma unroll
    for (int o = 16; o; o >>= 1) {
        p0 += __shfl_xor_sync(FULLMASK, p0, o);
        p1 += __shfl_xor_sync(FULLMASK, p1, o);
    }
    if (lane == 0) {
        out[(size_t)w * 2 + 0] = p0 + b[0];
        out[(size_t)w * 2 + 1] = p1 + b[1];
    }
}

// ---------------- host launch ----------------
extern "C" void kernel_launch(void* const* d_in, const int* in_sizes, int n_in,
                              void* d_out, int out_size) {
    const float* des    = (const float*)d_in[0];
    const float* num    = (const float*)d_in[2];
    const float* cat    = (const float*)d_in[3];
    const int*   ei     = (const int*)  d_in[4];
    const float* W_des  = (const float*)d_in[5];  const float* b_des  = (const float*)d_in[6];
    const float* W_num  = (const float*)d_in[7];  const float* b_num  = (const float*)d_in[8];
    const float* W_cat  = (const float*)d_in[9];  const float* b_cat  = (const float*)d_in[10];
    const float* W_in   = (const float*)d_in[11]; const float* b_in   = (const float*)d_in[12];
    const float* s1a_Wl = (const float*)d_in[13]; const float* s1a_bl = (const float*)d_in[14];
    const float* s1a_Wr = (const float*)d_in[15];
    const float* s1b_Wl = (const float*)d_in[16]; const float* s1b_bl = (const float*)d_in[17];
    const float* s1b_Wr = (const float*)d_in[18];
    const float* s2a_Wl = (const float*)d_in[19]; const float* s2a_bl = (const float*)d_in[20];
    const float* s2a_Wr = (const float*)d_in[21];
    const float* s2b_Wl = (const float*)d_in[22]; const float* s2b_bl = (const float*)d_in[23];
    const float* s2b_Wr = (const float*)d_in[24];
    const float* W_o1   = (const float*)d_in[25]; const float* b_o1   = (const float*)d_in[26];
    const float* W_o2   = (const float*)d_in[27]; const float* b_o2   = (const float*)d_in[28];
    float* out = (float*)d_out;

    int N = in_sizes[2] / 4;
    int E = in_sizes[4] / 2;
    const int* srcp = ei;
    const int* dstp = ei + E;

    float *f128, *xA, *tr, *h, *mh, *xB, *ob;
    int* cntp;
    cudaGetSymbolAddress((void**)&f128, g_f128);
    cudaGetSymbolAddress((void**)&xA, g_xA);
    cudaGetSymbolAddress((void**)&tr, g_tr);
    cudaGetSymbolAddress((void**)&h, g_h);
    cudaGetSymbolAddress((void**)&mh, g_mh);
    cudaGetSymbolAddress((void**)&xB, g_xB);
    cudaGetSymbolAddress((void**)&ob, g_ob);
    cudaGetSymbolAddress((void**)&cntp, g_cnt);

    cudaFuncSetAttribute(gemm_kernel<1, 1>, cudaFuncAttributeMaxDynamicSharedMemorySize, 100 * 1024);
    cudaFuncSetAttribute(mma_gemm_kernel<0>, cudaFuncAttributeMaxDynamicSharedMemorySize, MMA_TOT);
    cudaFuncSetAttribute(mma_gemm_kernel<1>, cudaFuncAttributeMaxDynamicSharedMemorySize, MMA_TOT);
    cudaFuncSetAttribute(mma_gemm_kernel<2>, cudaFuncAttributeMaxDynamicSharedMemorySize, MMA_TOT);

    int rowTiles64 = (N + 63) / 64;
    int gBd = rowTiles64 < 296 ? rowTiles64 : 296;
    int tcTiles = (N + 127) / 128;
    int gTC = tcTiles < 148 ? tcTiles : 148;
    int EB = (E + 255) / 256;
    int NB = (N + 255) / 256;
    int WB = (N * 32 + 255) / 256;
    size_t sm_des = (size_t)(768 * 32 + 32) * 4;

    // CSR build
    cudaMemsetAsync(cntp, 0, (size_t)N * sizeof(int));
    count_kernel<<<EB, 256>>>(dstp, E);
    scan_kernel<<<1, 1024>>>(N);
    scatter_kernel<<<EB, 256>>>(srcp, dstp, E);

    // front features
    front_small_kernel<<<NB, 256>>>(num, cat, W_num, b_num, W_cat, b_cat, N);
    gemm_kernel<1, 1><<<gBd, 256, sm_des>>>(des, 768, N, W_des, 768, 32,
                                            nullptr, 0, 0, 0, b_des, f128, 128, 768, 32);
    mma_gemm_kernel<1><<<gTC, 512, MMA_TOT>>>(f128, 128, N, W_in, 116, 128,
                                              nullptr, 0, 0, b_in, xA, 128);

    // SAGE block 1
    mma_gemm_kernel<0><<<gTC, 512, MMA_TOT>>>(xA, 128, N, s1a_Wl, 128, 64,
                                              s1a_Wr, 64, 1, nullptr, tr, 128);
    agg_a_kernel<<<WB, 256>>>(tr, s1a_bl, h, N);
    agg_b_kernel<<<WB, 256>>>(h, mh, N);
    mma_gemm_kernel<2><<<gTC, 512, MMA_TOT>>>(mh, 128, N, s1b_Wl, 64, 128,
                                              s1b_Wr, 128, 0, s1b_bl, xB, 128);

    // SAGE block 2
    mma_gemm_kernel<0><<<gTC, 512, MMA_TOT>>>(xB, 128, N, s2a_Wl, 128, 64,
                                              s2a_Wr, 64, 1, nullptr, tr, 128);
    agg_a_kernel<<<WB, 256>>>(tr, s2a_bl, h, N);
    agg_b_kernel<<<WB, 256>>>(h, mh, N);
    mma_gemm_kernel<2><<<gTC, 512, MMA_TOT>>>(mh, 128, N, s2b_Wl, 64, 128,
                                              s2b_Wr, 128, 0, s2b_bl, xA, 128);

    // output head
    mma_gemm_kernel<1><<<gTC, 512, MMA_TOT>>>(xA, 128, N, W_o1, 128, 128,
                                              nullptr, 0, 0, b_o1, ob, 128);
    out_kernel<<<WB, 256>>>(ob, W_o2, b_o2, out, N);
}